// round 5
// baseline (speedup 1.0000x reference)
#include <cuda_runtime.h>
#include <cuda_bf16.h>

#define IMG_H 1080
#define IMG_W 1920
#define THR 20.0f

// Run-of->=9 consecutive ones in a circular 16-bit mask.
// Shifts done as __umulhi (exact unsigned >>k) to run on the FMA pipe.
static __device__ __forceinline__ unsigned run9w(unsigned m16) {
    unsigned d = m16 * 0x10001u;                 // duplicate for circular wrap
    unsigned r = d & __umulhi(d, 0x80000000u);   // d >> 1  : runs >= 2
    r &= __umulhi(r, 0x40000000u);               // r >> 2  : runs >= 4
    r &= __umulhi(r, 0x10000000u);               // r >> 4  : runs >= 8
    r &= __umulhi(d, 0x01000000u);               // d >> 8  : runs >= 9
    return r & 0xFFFFu;
}

__global__ __launch_bounds__(96, 12)
void fast_score_kernel(const float* __restrict__ img, float* __restrict__ out, int N)
{
    const int DY[16] = { 0, 1, 2, 3, 3, 3, 2, 1, 0, -1, -2, -3, -3, -3, -2, -1};
    const int DX[16] = {-3, -3, -2, -1, 0, 1, 2, 3, 3, 3, 2, 1, 0, -1, -2, -3};

    int x0 = (blockIdx.x * blockDim.x + threadIdx.x) * 4;
    int y  = blockIdx.y;
    int n  = blockIdx.z;
    if (x0 >= IMG_W) return;

    const float* im = img + (size_t)n * IMG_H * IMG_W;
    float*       op = out + ((size_t)n * IMG_H + y) * IMG_W + x0;

    bool interior = (y >= 3) & (y <= IMG_H - 4) & (x0 >= 4) & (x0 + 7 <= IMG_W - 1);

    if (interior) {
        // Row tiles, trimmed to the columns each row's circle samples need:
        // R0 (dy=-3): [x0-1 .. x0+4]  R1 (dy=-2): [x0-2 .. x0+5]
        // R2 (dy=-1): [x0-4 .. x0+7]  R3 (dy= 0): [x0-4 .. x0+7]
        // R4 (dy=+1): [x0-4 .. x0+7]  R5 (dy=+2): [x0-2 .. x0+5]
        // R6 (dy=+3): [x0-1 .. x0+4]
        float R0[6], R1[8], R2[12], R3[12], R4[12], R5[8], R6[6];
        {
            const float* p;
            p = im + (size_t)(y - 3) * IMG_W + x0;
            R0[0] = p[-1];
            { float4 v = *(const float4*)p; R0[1]=v.x; R0[2]=v.y; R0[3]=v.z; R0[4]=v.w; }
            R0[5] = p[4];
            p = im + (size_t)(y - 2) * IMG_W + x0;
            { float2 v = *(const float2*)(p - 2); R1[0]=v.x; R1[1]=v.y; }
            { float4 v = *(const float4*)p;       R1[2]=v.x; R1[3]=v.y; R1[4]=v.z; R1[5]=v.w; }
            { float2 v = *(const float2*)(p + 4); R1[6]=v.x; R1[7]=v.y; }
            p = im + (size_t)(y - 1) * IMG_W + (x0 - 4);
            { float4 a=*(const float4*)p, b=*(const float4*)(p+4), c=*(const float4*)(p+8);
              R2[0]=a.x;R2[1]=a.y;R2[2]=a.z;R2[3]=a.w;R2[4]=b.x;R2[5]=b.y;R2[6]=b.z;R2[7]=b.w;
              R2[8]=c.x;R2[9]=c.y;R2[10]=c.z;R2[11]=c.w; }
            p = im + (size_t)(y) * IMG_W + (x0 - 4);
            { float4 a=*(const float4*)p, b=*(const float4*)(p+4), c=*(const float4*)(p+8);
              R3[0]=a.x;R3[1]=a.y;R3[2]=a.z;R3[3]=a.w;R3[4]=b.x;R3[5]=b.y;R3[6]=b.z;R3[7]=b.w;
              R3[8]=c.x;R3[9]=c.y;R3[10]=c.z;R3[11]=c.w; }
            p = im + (size_t)(y + 1) * IMG_W + (x0 - 4);
            { float4 a=*(const float4*)p, b=*(const float4*)(p+4), c=*(const float4*)(p+8);
              R4[0]=a.x;R4[1]=a.y;R4[2]=a.z;R4[3]=a.w;R4[4]=b.x;R4[5]=b.y;R4[6]=b.z;R4[7]=b.w;
              R4[8]=c.x;R4[9]=c.y;R4[10]=c.z;R4[11]=c.w; }
            p = im + (size_t)(y + 2) * IMG_W + x0;
            { float2 v = *(const float2*)(p - 2); R5[0]=v.x; R5[1]=v.y; }
            { float4 v = *(const float4*)p;       R5[2]=v.x; R5[3]=v.y; R5[4]=v.z; R5[5]=v.w; }
            { float2 v = *(const float2*)(p + 4); R5[6]=v.x; R5[7]=v.y; }
            p = im + (size_t)(y + 3) * IMG_W + x0;
            R6[0] = p[-1];
            { float4 v = *(const float4*)p; R6[1]=v.x; R6[2]=v.y; R6[3]=v.z; R6[4]=v.w; }
            R6[5] = p[4];
        }

        float4 res;
        float* resp = (float*)&res;
#pragma unroll
        for (int p = 0; p < 4; p++) {
            float ctr = R3[p + 4];
            float d[16];
            d[0]  = R3[p + 1] - ctr;   // (0,-3)
            d[1]  = R4[p + 1] - ctr;   // (1,-3)
            d[2]  = R5[p + 0] - ctr;   // (2,-2)
            d[3]  = R6[p + 0] - ctr;   // (3,-1)
            d[4]  = R6[p + 1] - ctr;   // (3, 0)
            d[5]  = R6[p + 2] - ctr;   // (3, 1)
            d[6]  = R5[p + 4] - ctr;   // (2, 2)
            d[7]  = R4[p + 7] - ctr;   // (1, 3)
            d[8]  = R3[p + 7] - ctr;   // (0, 3)
            d[9]  = R2[p + 7] - ctr;   // (-1,3)
            d[10] = R1[p + 4] - ctr;   // (-2,2)
            d[11] = R0[p + 2] - ctr;   // (-3,1)
            d[12] = R0[p + 1] - ctr;   // (-3,0)
            d[13] = R0[p + 0] - ctr;   // (-3,-1)
            d[14] = R1[p + 0] - ctr;   // (-2,-2)
            d[15] = R2[p + 1] - ctr;   // (-1,-3)

            // Sign gathers: one SHF per bit (ALU pipe).
            // nd bit i = (d[i] < 0)
            // ns bit i = signbit(fma(d,d,-400)) = (d*d < 400) = (|d| < 20) [exact;
            //            |d|==20 -> +0 -> strong, matching the reference >= / <=]
            unsigned nd = 0u, ns = 0u;
#pragma unroll
            for (int i = 15; i >= 0; i--) {
                float s = __fmaf_rn(d[i], d[i], -400.0f);   // FMA pipe
                nd = __funnelshift_l(__float_as_uint(d[i]), nd, 1);
                ns = __funnelshift_l(__float_as_uint(s),    ns, 1);
            }

            unsigned dark   = ~ns & ~nd & 0xFFFFu;  // strong & (d >= 0)  [1 LOP3]
            unsigned bright = ~ns &  nd;            // strong & (d <  0)  [1 LOP3]

            unsigned det = run9w(dark) | run9w(bright);
            resp[p] = __uint_as_float(min(det, 1u) * 0x3F800000u);
        }
        *(float4*)op = res;
    } else {
        // Border path: scalar loads with replicate-clamp (rare; known-good form).
#pragma unroll
        for (int p = 0; p < 4; p++) {
            int x = x0 + p;
            float center = __ldg(im + (size_t)y * IMG_W + x);
            unsigned dark = 0u, bright = 0u;
#pragma unroll
            for (int i = 0; i < 16; i++) {
                int yy = min(max(y + DY[i], 0), IMG_H - 1);
                int xx = min(max(x + DX[i], 0), IMG_W - 1);
                float diff = __ldg(im + (size_t)yy * IMG_W + xx) - center;
                if (diff >=  THR) dark   |= (1u << i);
                if (diff <= -THR) bright |= (1u << i);
            }
            unsigned det = run9w(dark) | run9w(bright);
            op[p] = __uint_as_float(min(det, 1u) * 0x3F800000u);
        }
    }
}

extern "C" void kernel_launch(void* const* d_in, const int* in_sizes, int n_in,
                              void* d_out, int out_size)
{
    const float* img = (const float*)d_in[0];
    float* out = (float*)d_out;
    int N = in_sizes[0] / (IMG_H * IMG_W);

    dim3 block(96, 1, 1);
    // 1920 / 4 px-per-thread = 480 threads along x -> exactly 5 blocks of 96
    dim3 grid(IMG_W / 4 / 96, IMG_H, N);
    fast_score_kernel<<<grid, block>>>(img, out, N);
}

// round 6
// speedup vs baseline: 1.0838x; 1.0838x over previous
#include <cuda_runtime.h>
#include <cuda_bf16.h>

#define IMG_H 1080
#define IMG_W 1920
#define THR 20.0f

// Run-of->=9 consecutive ones in a circular 16-bit mask.
// Shifts done as __umulhi (exact unsigned >>k) to run on the FMA pipe.
static __device__ __forceinline__ unsigned run9w(unsigned m16) {
    unsigned d = m16 * 0x10001u;                 // duplicate for circular wrap
    unsigned r = d & __umulhi(d, 0x80000000u);   // d >> 1  : runs >= 2
    r &= __umulhi(r, 0x40000000u);               // r >> 2  : runs >= 4
    r &= __umulhi(r, 0x10000000u);               // r >> 4  : runs >= 8
    r &= __umulhi(d, 0x01000000u);               // d >> 8  : runs >= 9
    return r & 0xFFFFu;
}

// From 16 circle diffs -> 1.0f/0.0f detection.
static __device__ __forceinline__ float detect16(const float* d) {
    unsigned nd = 0u, ns = 0u;
#pragma unroll
    for (int i = 15; i >= 0; i--) {
        float s = __fmaf_rn(d[i], d[i], -400.0f);   // sign: |d|<20 (exact)
        nd = __funnelshift_l(__float_as_uint(d[i]), nd, 1);
        ns = __funnelshift_l(__float_as_uint(s),    ns, 1);
    }
    unsigned dark   = ~ns & ~nd & 0xFFFFu;          // strong & d>=0
    unsigned bright = ~ns &  nd;                    // strong & d<0
    unsigned det = run9w(dark) | run9w(bright);
    return __uint_as_float(min(det, 1u) * 0x3F800000u);
}

__global__ __launch_bounds__(96)
void fast_score_kernel(const float* __restrict__ img, float* __restrict__ out, int N)
{
    const int DY[16] = { 0, 1, 2, 3, 3, 3, 2, 1, 0, -1, -2, -3, -3, -3, -2, -1};
    const int DX[16] = {-3, -3, -2, -1, 0, 1, 2, 3, 3, 3, 2, 1, 0, -1, -2, -3};

    int x0 = (blockIdx.x * blockDim.x + threadIdx.x) * 4;
    int y0 = blockIdx.y * 2;            // this thread handles rows y0 and y0+1
    int n  = blockIdx.z;

    const float* im = img + (size_t)n * IMG_H * IMG_W;
    float* op0 = out + ((size_t)n * IMG_H + y0) * IMG_W + x0;
    float* op1 = op0 + IMG_W;

    bool interior = (y0 >= 4) & (y0 <= IMG_H - 6) & (x0 >= 4) & (x0 <= IMG_W - 8);

    if (interior) {
        // Union tile for both center rows:
        // T0: y0-3 [x0-1..x0+4](6)   T1: y0-2 [x0-2..x0+5](8)
        // T2: y0-1 [x0-4..x0+7](12)  T3: y0   [x0-4..x0+7](12)
        // T4: y0+1 [x0-4..x0+7](12)  T5: y0+2 [x0-4..x0+7](12)
        // T6: y0+3 [x0-2..x0+5](8)   T7: y0+4 [x0-1..x0+4](6)
        float T0[6], T1[8], T2[12], T3[12], T4[12], T5[12], T6[8], T7[6];
        {
            const float* p;
            p = im + (size_t)(y0 - 3) * IMG_W + x0;
            T0[0] = p[-1];
            { float4 v = *(const float4*)p; T0[1]=v.x; T0[2]=v.y; T0[3]=v.z; T0[4]=v.w; }
            T0[5] = p[4];
            p = im + (size_t)(y0 - 2) * IMG_W + x0;
            { float2 v = *(const float2*)(p - 2); T1[0]=v.x; T1[1]=v.y; }
            { float4 v = *(const float4*)p;       T1[2]=v.x; T1[3]=v.y; T1[4]=v.z; T1[5]=v.w; }
            { float2 v = *(const float2*)(p + 4); T1[6]=v.x; T1[7]=v.y; }
            p = im + (size_t)(y0 - 1) * IMG_W + (x0 - 4);
            { float4 a=*(const float4*)p, b=*(const float4*)(p+4), c=*(const float4*)(p+8);
              T2[0]=a.x;T2[1]=a.y;T2[2]=a.z;T2[3]=a.w;T2[4]=b.x;T2[5]=b.y;T2[6]=b.z;T2[7]=b.w;
              T2[8]=c.x;T2[9]=c.y;T2[10]=c.z;T2[11]=c.w; }
            p = im + (size_t)(y0) * IMG_W + (x0 - 4);
            { float4 a=*(const float4*)p, b=*(const float4*)(p+4), c=*(const float4*)(p+8);
              T3[0]=a.x;T3[1]=a.y;T3[2]=a.z;T3[3]=a.w;T3[4]=b.x;T3[5]=b.y;T3[6]=b.z;T3[7]=b.w;
              T3[8]=c.x;T3[9]=c.y;T3[10]=c.z;T3[11]=c.w; }
            p = im + (size_t)(y0 + 1) * IMG_W + (x0 - 4);
            { float4 a=*(const float4*)p, b=*(const float4*)(p+4), c=*(const float4*)(p+8);
              T4[0]=a.x;T4[1]=a.y;T4[2]=a.z;T4[3]=a.w;T4[4]=b.x;T4[5]=b.y;T4[6]=b.z;T4[7]=b.w;
              T4[8]=c.x;T4[9]=c.y;T4[10]=c.z;T4[11]=c.w; }
            p = im + (size_t)(y0 + 2) * IMG_W + (x0 - 4);
            { float4 a=*(const float4*)p, b=*(const float4*)(p+4), c=*(const float4*)(p+8);
              T5[0]=a.x;T5[1]=a.y;T5[2]=a.z;T5[3]=a.w;T5[4]=b.x;T5[5]=b.y;T5[6]=b.z;T5[7]=b.w;
              T5[8]=c.x;T5[9]=c.y;T5[10]=c.z;T5[11]=c.w; }
            p = im + (size_t)(y0 + 3) * IMG_W + x0;
            { float2 v = *(const float2*)(p - 2); T6[0]=v.x; T6[1]=v.y; }
            { float4 v = *(const float4*)p;       T6[2]=v.x; T6[3]=v.y; T6[4]=v.z; T6[5]=v.w; }
            { float2 v = *(const float2*)(p + 4); T6[6]=v.x; T6[7]=v.y; }
            p = im + (size_t)(y0 + 4) * IMG_W + x0;
            T7[0] = p[-1];
            { float4 v = *(const float4*)p; T7[1]=v.x; T7[2]=v.y; T7[3]=v.z; T7[4]=v.w; }
            T7[5] = p[4];
        }

        float4 res0, res1;
        float* r0p = (float*)&res0;
        float* r1p = (float*)&res1;
#pragma unroll
        for (int p = 0; p < 4; p++) {
            float d[16];
            // ---- center row y0 (roles: R0..R6 = T0..T6) ----
            {
                float ctr = T3[p + 4];
                d[0]  = T3[p + 1] - ctr;   // (0,-3)
                d[1]  = T4[p + 1] - ctr;   // (1,-3)
                d[2]  = T5[p + 2] - ctr;   // (2,-2)  T5 base x0-4
                d[3]  = T6[p + 1] - ctr;   // (3,-1)  T6 base x0-2
                d[4]  = T6[p + 2] - ctr;   // (3, 0)
                d[5]  = T6[p + 3] - ctr;   // (3, 1)
                d[6]  = T5[p + 6] - ctr;   // (2, 2)
                d[7]  = T4[p + 7] - ctr;   // (1, 3)
                d[8]  = T3[p + 7] - ctr;   // (0, 3)
                d[9]  = T2[p + 7] - ctr;   // (-1,3)
                d[10] = T1[p + 4] - ctr;   // (-2,2)
                d[11] = T0[p + 2] - ctr;   // (-3,1)
                d[12] = T0[p + 1] - ctr;   // (-3,0)
                d[13] = T0[p + 0] - ctr;   // (-3,-1)
                d[14] = T1[p + 0] - ctr;   // (-2,-2)
                d[15] = T2[p + 1] - ctr;   // (-1,-3)
                r0p[p] = detect16(d);
            }
            // ---- center row y0+1 (roles: R0..R6 = T1..T7) ----
            {
                float ctr = T4[p + 4];
                d[0]  = T4[p + 1] - ctr;   // (0,-3)
                d[1]  = T5[p + 1] - ctr;   // (1,-3)  T5 base x0-4
                d[2]  = T6[p + 0] - ctr;   // (2,-2)  T6 base x0-2
                d[3]  = T7[p + 0] - ctr;   // (3,-1)  T7 base x0-1
                d[4]  = T7[p + 1] - ctr;   // (3, 0)
                d[5]  = T7[p + 2] - ctr;   // (3, 1)
                d[6]  = T6[p + 4] - ctr;   // (2, 2)
                d[7]  = T5[p + 7] - ctr;   // (1, 3)
                d[8]  = T4[p + 7] - ctr;   // (0, 3)
                d[9]  = T3[p + 7] - ctr;   // (-1,3)
                d[10] = T2[p + 6] - ctr;   // (-2,2)  T2 base x0-4
                d[11] = T1[p + 3] - ctr;   // (-3,1)  T1 base x0-2
                d[12] = T1[p + 2] - ctr;   // (-3,0)
                d[13] = T1[p + 1] - ctr;   // (-3,-1)
                d[14] = T2[p + 2] - ctr;   // (-2,-2)
                d[15] = T3[p + 1] - ctr;   // (-1,-3)
                r1p[p] = detect16(d);
            }
        }
        *(float4*)op0 = res0;
        *(float4*)op1 = res1;
    } else {
        // Border path: scalar loads with replicate-clamp (rare).
#pragma unroll
        for (int rr = 0; rr < 2; rr++) {
            int y = y0 + rr;
            float* op = (rr == 0) ? op0 : op1;
#pragma unroll
            for (int p = 0; p < 4; p++) {
                int x = x0 + p;
                float center = __ldg(im + (size_t)y * IMG_W + x);
                unsigned dark = 0u, bright = 0u;
#pragma unroll
                for (int i = 0; i < 16; i++) {
                    int yy = min(max(y + DY[i], 0), IMG_H - 1);
                    int xx = min(max(x + DX[i], 0), IMG_W - 1);
                    float diff = __ldg(im + (size_t)yy * IMG_W + xx) - center;
                    if (diff >=  THR) dark   |= (1u << i);
                    if (diff <= -THR) bright |= (1u << i);
                }
                unsigned det = run9w(dark) | run9w(bright);
                op[p] = __uint_as_float(min(det, 1u) * 0x3F800000u);
            }
        }
    }
}

extern "C" void kernel_launch(void* const* d_in, const int* in_sizes, int n_in,
                              void* d_out, int out_size)
{
    const float* img = (const float*)d_in[0];
    float* out = (float*)d_out;
    int N = in_sizes[0] / (IMG_H * IMG_W);

    dim3 block(96, 1, 1);
    // x: 1920/4 px-per-thread = 480 threads -> 5 blocks of 96
    // y: two rows per thread -> 540
    dim3 grid(IMG_W / 4 / 96, IMG_H / 2, N);
    fast_score_kernel<<<grid, block>>>(img, out, N);
}